// round 16
// baseline (speedup 1.0000x reference)
#include <cuda_runtime.h>
#include <cuda_fp16.h>

#define FULL_MASK 0xFFFFFFFFu
typedef unsigned long long u64;

// ---------- packed f32x2 helpers (sm_100a) ----------
__device__ __forceinline__ u64 pack2(float a, float b) {
    u64 d; asm("mov.b64 %0, {%1, %2};" : "=l"(d) : "f"(a), "f"(b)); return d;
}
__device__ __forceinline__ void unpack2(u64 v, float& a, float& b) {
    asm("mov.b64 {%0, %1}, %2;" : "=f"(a), "=f"(b) : "l"(v));
}
__device__ __forceinline__ u64 fma2(u64 a, u64 b, u64 c) {
    u64 d; asm("fma.rn.f32x2 %0, %1, %2, %3;" : "=l"(d) : "l"(a), "l"(b), "l"(c)); return d;
}
__device__ __forceinline__ u64 mul2(u64 a, u64 b) {
    u64 d; asm("mul.rn.f32x2 %0, %1, %2;" : "=l"(d) : "l"(a), "l"(b)); return d;
}
__device__ __forceinline__ u64 add2(u64 a, u64 b) {
    u64 d; asm("add.rn.f32x2 %0, %1, %2;" : "=l"(d) : "l"(a), "l"(b)); return d;
}

// 16-lane-per-site layout. Warp = 2 sites (lane bit4 = site s; l4 = lane&15).
// Per-thread state: 16 f32x2 regs. Amp index i = l4*32 + k*2 + p:
//   q0..q3 <-> l4 bits 3..0, q4..q7 <-> k bits 3..0, q8 <-> pair bit p.
// Layer-1 CNOT chain q0->1->2->3 is DEFERRED (logical lam4 = 4-bit prefix-xor).
// Variational RYs in TANGENT FORM (18 cos factors -> one S^2 at measurement).
// Layer-1's four lane RYs folded into the build via transfer-matrix DP.
// NEW: ring q8->0 fused into layer-2's q0 lane RY (same physical mask 12);
// layer-2's q1..q3 partner exchanges compressed to f16x2 (partner is scaled
// by |tan| <= 0.151, so f16 rounding contributes ~2e-5 rel per RY).
__global__ void __launch_bounds__(128, 9)
quanv_main(const float* __restrict__ x, const float* __restrict__ qp,
           float* __restrict__ out) {
    __shared__ float s_vt[2][3][9];   // tan(theta/2) for layers 1,2
    __shared__ float s_h0[3][9];      // folded layer-0 half-angles
    __shared__ float s_s2[3];         // (prod cos)^2 per channel

    const int tid = threadIdx.x;

    // ---- per-block prep ----
    if (tid < 27) {
        int cc = tid / 9, q = tid % 9;
        s_h0[cc][q] = 0.5f * qp[cc * 16 + q];
    } else if (tid < 81) {
        int u = tid - 27;
        int l = u / 27;                         // 0 -> qp layer 1, 1 -> layer 2
        int cc = (u % 27) / 9;
        int q = u % 9;
        float s, co;
        __sincosf(0.5f * qp[((l + 1) * 3 + cc) * 16 + q], &s, &co);
        s_vt[l][cc][q] = __fdividef(s, co);
    } else if (tid < 84) {
        int cc = tid - 81;
        float p = 1.0f;
#pragma unroll
        for (int l = 1; l <= 2; ++l)
#pragma unroll
            for (int q = 0; q < 9; ++q)
                p *= __cosf(0.5f * qp[(l * 3 + cc) * 16 + q]);
        s_s2[cc] = p * p;
    }
    __syncthreads();

    const int lane = tid & 31;
    const int l4   = lane & 15;
    const int s    = lane >> 4;                       // site within pair
    const int unit = (blockIdx.x * 128 + tid) >> 5;   // 0..12287
    const int c   = unit % 3;
    const int wp  = (unit / 3) & 15;
    const int shh = (unit / 48) & 31;
    const int b   = unit / 1536;
    const int sw  = 2 * wp + s;                       // this half's w

    const int c0 = (l4 >> 3) & 1, c1 = (l4 >> 2) & 1,
              c2 = (l4 >> 1) & 1, c3 = l4 & 1;

    // --- Build phase 1: qubits 0..4 + layer-1 lane-RY fold -> M(k3,p) ---
    float M00, M01, M10, M11;   // M[k3][p]
    {
        float ecl[5], esl[5];
#pragma unroll
        for (int q = 0; q < 5; ++q) {
            const int di = q / 3 - 1, dj = q % 3 - 1;
            const int hi = shh + di, wj = sw + dj;
            float px = 0.0f;
            if ((unsigned)hi < 32u && (unsigned)wj < 32u)
                px = x[((b * 32 + hi) * 32 + wj) * 3 + c];
            __sincosf(fmaf(1.5707963267948966f, px, s_h0[c][q]), &esl[q], &ecl[q]);
        }
        const float t0 = s_vt[0][c][0], t1 = s_vt[0][c][1],
                    t2 = s_vt[0][c][2], t3 = s_vt[0][c][3];
        const float u0 = c0 ? t0 : -t0;
        const float u1 = c1 ? t1 : -t1;
        const float u2 = c2 ? t2 : -t2;
        const float u3 = c3 ? t3 : -t3;
        const int b2 = c2 ^ c1, b3 = c3 ^ c2;
        const float F2a = b2 ? esl[2] : ecl[2], F2b = b2 ? ecl[2] : esl[2];
        const float F3a = b3 ? esl[3] : ecl[3], F3b = b3 ? ecl[3] : esl[3];
        const float F4a = c3 ? esl[4] : ecl[4], F4b = c3 ? ecl[4] : esl[4];
#pragma unroll
        for (int p = 0; p < 2; ++p) {
            const int b0 = c0 ^ p, b1 = (c1 ^ c0) ^ p;
            const float F0a = b0 ? esl[0] : ecl[0], F0b = b0 ? ecl[0] : esl[0];
            const float F1a = b1 ? esl[1] : ecl[1], F1b = b1 ? ecl[1] : esl[1];
            const float D10 = fmaf(u0, F0b * F1b, F0a * F1a);
            const float D11 = fmaf(u0, F0b * F1a, F0a * F1b);
            const float D20 = fmaf(u1, D11 * F2b, D10 * F2a);
            const float D21 = fmaf(u1, D11 * F2a, D10 * F2b);
            const float D30 = fmaf(u2, D21 * F3b, D20 * F3a);
            const float D31 = fmaf(u2, D21 * F3a, D20 * F3b);
            const float m0 = fmaf(u3, D31 * F4b, D30 * F4a);   // k3=0
            const float m1 = fmaf(u3, D31 * F4a, D30 * F4b);   // k3=1
            if (p == 0) { M00 = m0; M10 = m1; }
            else        { M01 = m0; M11 = m1; }
        }
    }

    // --- Build phase 2: qubits 5..8 -> per-k factors, write state ---
    u64 st[16];
    {
        float ech[4], esh[4];
#pragma unroll
        for (int q = 5; q < 9; ++q) {
            const int di = q / 3 - 1, dj = q % 3 - 1;
            const int hi = shh + di, wj = sw + dj;
            float px = 0.0f;
            if ((unsigned)hi < 32u && (unsigned)wj < 32u)
                px = x[((b * 32 + hi) * 32 + wj) * 3 + c];
            __sincosf(fmaf(1.5707963267948966f, px, s_h0[c][q]), &esh[q - 5], &ech[q - 5]);
        }
        const u64 MM0 = pack2(M00, M01);         // k3=0: (p=0, p=1)
        const u64 MM1 = pack2(M10, M11);         // k3=1
        const u64 T8a = pack2(ech[3], esh[3]);   // k0=0: b8=p
        const u64 T8b = pack2(esh[3], ech[3]);   // k0=1: b8=p^1
#pragma unroll
        for (int k = 0; k < 16; ++k) {
            const int k3 = (k >> 3) & 1, k2 = (k >> 2) & 1,
                      k1 = (k >> 1) & 1, k0 = k & 1;
            const float m = ((k2 ^ k3) ? esh[0] : ech[0]) *
                            ((k1 ^ k2) ? esh[1] : ech[1]) *
                            ((k0 ^ k1) ? esh[2] : ech[2]);
            st[k] = mul2(mul2(k3 ? MM1 : MM0, pack2(m, m)), k0 ? T8b : T8a);
        }
    }

    const int lam4 = l4 ^ (l4 >> 1) ^ (l4 >> 2) ^ (l4 >> 3);

    // ========== Layer 1 (lane RYs already folded into the build) ==========
    // reg RYs q4..q7: a' = a - t*b ; b' = b + t*a
#pragma unroll
    for (int q = 4; q < 8; ++q) {
        const int m2 = 1 << (7 - q);
        const float t = s_vt[0][c][q];
        const u64 tp = pack2(t, t), tn = pack2(-t, -t);
#pragma unroll
        for (int k = 0; k < 16; ++k)
            if (!(k & m2)) {
                const u64 a = st[k], bb = st[k + m2];
                st[k]      = fma2(tn, bb, a);
                st[k + m2] = fma2(tp, a, bb);
            }
    }
    // pair RY q8: st' = st + (-t,+t)*swap(st)
    {
        const float t = s_vt[0][c][8];
        const u64 tpm = pack2(-t, t);
#pragma unroll
        for (int k = 0; k < 16; ++k) {
            float a, bb; unpack2(st[k], a, bb);
            st[k] = fma2(tpm, pack2(bb, a), st[k]);
        }
    }

    // --- Layer-1 CNOT ring ---
    // q0..q3 lane segment: DEFERRED. q3->q4: ctrl = popc(l4)&1, tgt k bit 3.
    {
        const bool hi = (__popc(l4) & 1) != 0;
#pragma unroll
        for (int k = 0; k < 8; ++k) {
            const u64 a = st[k], bb = st[k + 8];
            st[k]     = hi ? bb : a;
            st[k + 8] = hi ? a : bb;
        }
    }
    // q4->5, q5->6, q6->7: register renames (free)
    { u64 t;
      t = st[ 8]; st[ 8] = st[12]; st[12] = t;
      t = st[ 9]; st[ 9] = st[13]; st[13] = t;
      t = st[10]; st[10] = st[14]; st[14] = t;
      t = st[11]; st[11] = st[15]; st[15] = t; }
    { u64 t;
      t = st[ 4]; st[ 4] = st[ 6]; st[ 6] = t;
      t = st[ 5]; st[ 5] = st[ 7]; st[ 7] = t;
      t = st[12]; st[12] = st[14]; st[14] = t;
      t = st[13]; st[13] = st[15]; st[15] = t; }
    { u64 t;
      t = st[ 2]; st[ 2] = st[ 3]; st[ 3] = t;
      t = st[ 6]; st[ 6] = st[ 7]; st[ 7] = t;
      t = st[10]; st[10] = st[11]; st[11] = t;
      t = st[14]; st[14] = st[15]; st[15] = t; }
    // q7->q8: half-swap odd-k vecs
#pragma unroll
    for (int k = 1; k < 16; k += 2) {
        float a, bb; unpack2(st[k], a, bb);
        st[k] = pack2(bb, a);
    }
    // q8->q0 ring shuffle is FUSED into the next block.

    // ========== Layer 2 (deferred space, tangent form) ==========
    // q0 lane RY fused with ring q8->0 (both physical mask 12, exact f32):
    //   a' = a + u*shfl(a,12) ;  b' = shfl(B,12) + u*B   (B = pre-ring b-half)
    {
        const float t = s_vt[1][c][0];
        const float u = (lam4 & 8) ? t : -t;
#pragma unroll
        for (int k = 0; k < 16; ++k) {
            float a, bb; unpack2(st[k], a, bb);
            const float pa = __shfl_xor_sync(FULL_MASK, a, 12);
            const float pB = __shfl_xor_sync(FULL_MASK, bb, 12);
            st[k] = pack2(fmaf(u, pa, a), fmaf(u, bb, pB));
        }
    }
    // q1..q3 lane RYs with f16x2-compressed partner exchange (partner scaled
    // by t, |t|<=0.151, so f16 rounding is attenuated ~7x).
    {
        const int pmask[3] = {6, 3, 1};
        const int lmask[3] = {4, 2, 1};
#pragma unroll
        for (int qq = 0; qq < 3; ++qq) {
            const int pm = pmask[qq];
            const float t = s_vt[1][c][qq + 1];
            const float sts = (lam4 & lmask[qq]) ? t : -t;
            const u64 t2 = pack2(sts, sts);
#pragma unroll
            for (int k = 0; k < 16; ++k) {
                float a, bb; unpack2(st[k], a, bb);
                __half2 hv = __floats2half2_rn(a, bb);   // .x = a (lo), .y = bb
                unsigned hw = reinterpret_cast<unsigned&>(hv);
                unsigned pw = __shfl_xor_sync(FULL_MASK, hw, pm);
                __half2 ph = reinterpret_cast<__half2&>(pw);
                float2 pf = __half22float2(ph);          // .x = partner-a
                st[k] = fma2(t2, pack2(pf.x, pf.y), st[k]);
            }
        }
    }
    // reg RYs q4..q7
#pragma unroll
    for (int q = 4; q < 8; ++q) {
        const int m2 = 1 << (7 - q);
        const float t = s_vt[1][c][q];
        const u64 tp = pack2(t, t), tn = pack2(-t, -t);
#pragma unroll
        for (int k = 0; k < 16; ++k)
            if (!(k & m2)) {
                const u64 a = st[k], bb = st[k + m2];
                st[k]      = fma2(tn, bb, a);
                st[k + m2] = fma2(tp, a, bb);
            }
    }
    // pair RY q8
    {
        const float t = s_vt[1][c][8];
        const u64 tpm = pack2(-t, t);
#pragma unroll
        for (int k = 0; k < 16; ++k) {
            float a, bb; unpack2(st[k], a, bb);
            st[k] = fma2(tpm, pack2(bb, a), st[k]);
        }
    }

    // --- Measurement (diagonal Pauli strings; cos product restored as S^2) ---
    u64 accE = 0ull, accO = 0ull;
#pragma unroll
    for (int k = 0; k < 16; ++k) {
        const u64 p = mul2(st[k], st[k]);
        if ((0x9669 >> k) & 1) accE = add2(accE, p);   // popc(k) even
        else                   accO = add2(accO, p);
    }
    float e0, e1, o0, o1;
    unpack2(accE, e0, e1); unpack2(accO, o0, o1);
    const float s2 = s_s2[c];
    const float sp = e0 + o1, sm = e1 + o0;
    const float tot = (sp + sm) * s2;
    const float dif = (sp - sm) * s2;

    // z0: per-half 4-level reduce
    float u = (__popc(lam4 & 7) & 1) ? -dif : dif;
    u += __shfl_xor_sync(FULL_MASK, u, 8);
    u += __shfl_xor_sync(FULL_MASK, u, 4);
    u += __shfl_xor_sync(FULL_MASK, u, 2);
    u += __shfl_xor_sync(FULL_MASK, u, 1);

    // z1/z2 factored: reduce over lam1-class subgroup {1,6,10}, cross mask 2
    float y = (__popc(lam4 & 12) & 1) ? -tot : tot;
    y += __shfl_xor_sync(FULL_MASK, y, 1);
    y += __shfl_xor_sync(FULL_MASK, y, 6);
    y += __shfl_xor_sync(FULL_MASK, y, 10);
    const float w = __shfl_xor_sync(FULL_MASK, y, 2);

    if (l4 == 0) {                       // lanes 0 (site A) and 16 (site B)
        const int base = 3 * (((b * 32 + shh) * 32 + 2 * wp + s) * 3 + c);
        out[base + 0] = u;
        out[base + 1] = y + w;           // lam4(0)=0 -> lam1-class 0
        out[base + 2] = y - w;
    }
}

extern "C" void kernel_launch(void* const* d_in, const int* in_sizes, int n_in,
                              void* d_out, int out_size) {
    const float* x  = (const float*)d_in[0];
    const float* qp = (const float*)d_in[1];
    float* out = (float*)d_out;
    // 12288 site-pair warps / 4 warps per 128-thread block = 3072 blocks
    quanv_main<<<3072, 128>>>(x, qp, out);
}

// round 17
// speedup vs baseline: 1.1092x; 1.1092x over previous
#include <cuda_runtime.h>

#define FULL_MASK 0xFFFFFFFFu
typedef unsigned long long u64;

// ---------- packed f32x2 helpers (sm_100a) ----------
__device__ __forceinline__ u64 pack2(float a, float b) {
    u64 d; asm("mov.b64 %0, {%1, %2};" : "=l"(d) : "f"(a), "f"(b)); return d;
}
__device__ __forceinline__ void unpack2(u64 v, float& a, float& b) {
    asm("mov.b64 {%0, %1}, %2;" : "=f"(a), "=f"(b) : "l"(v));
}
__device__ __forceinline__ u64 fma2(u64 a, u64 b, u64 c) {
    u64 d; asm("fma.rn.f32x2 %0, %1, %2, %3;" : "=l"(d) : "l"(a), "l"(b), "l"(c)); return d;
}
__device__ __forceinline__ u64 mul2(u64 a, u64 b) {
    u64 d; asm("mul.rn.f32x2 %0, %1, %2;" : "=l"(d) : "l"(a), "l"(b)); return d;
}
__device__ __forceinline__ u64 add2(u64 a, u64 b) {
    u64 d; asm("add.rn.f32x2 %0, %1, %2;" : "=l"(d) : "l"(a), "l"(b)); return d;
}

// 16-lane-per-site layout. Warp = 2 sites (lane bit4 = site s; l4 = lane&15).
// Per-thread state: 16 f32x2 regs. Amp index i = l4*32 + k*2 + p:
//   q0..q3 <-> l4 bits 3..0, q4..q7 <-> k bits 3..0, q8 <-> pair bit p.
// Layer-1 CNOT chain q0->1->2->3 is DEFERRED (logical lam4 = 4-bit prefix-xor).
// Variational RYs in TANGENT FORM (18 cos factors -> one S^2 at measurement).
// Layer-1's four lane RYs folded into the build via transfer-matrix DP.
// Ring q8->0 fused into layer-2's q0 lane RY (same physical mask 12, exact).
// All exchanges are f32 (fp16 compression tried in R16: issue-count negative).
__global__ void __launch_bounds__(128, 9)
quanv_main(const float* __restrict__ x, const float* __restrict__ qp,
           float* __restrict__ out) {
    __shared__ float s_vt[2][3][9];   // tan(theta/2) for layers 1,2
    __shared__ float s_h0[3][9];      // folded layer-0 half-angles
    __shared__ float s_s2[3];         // (prod cos)^2 per channel

    const int tid = threadIdx.x;

    // ---- per-block prep ----
    if (tid < 27) {
        int cc = tid / 9, q = tid % 9;
        s_h0[cc][q] = 0.5f * qp[cc * 16 + q];
    } else if (tid < 81) {
        int u = tid - 27;
        int l = u / 27;                         // 0 -> qp layer 1, 1 -> layer 2
        int cc = (u % 27) / 9;
        int q = u % 9;
        float s, co;
        __sincosf(0.5f * qp[((l + 1) * 3 + cc) * 16 + q], &s, &co);
        s_vt[l][cc][q] = __fdividef(s, co);
    } else if (tid < 84) {
        int cc = tid - 81;
        float p = 1.0f;
#pragma unroll
        for (int l = 1; l <= 2; ++l)
#pragma unroll
            for (int q = 0; q < 9; ++q)
                p *= __cosf(0.5f * qp[(l * 3 + cc) * 16 + q]);
        s_s2[cc] = p * p;
    }
    __syncthreads();

    const int lane = tid & 31;
    const int l4   = lane & 15;
    const int s    = lane >> 4;                       // site within pair
    const int unit = (blockIdx.x * 128 + tid) >> 5;   // 0..12287
    const int c   = unit % 3;
    const int wp  = (unit / 3) & 15;
    const int shh = (unit / 48) & 31;
    const int b   = unit / 1536;
    const int sw  = 2 * wp + s;                       // this half's w

    const int c0 = (l4 >> 3) & 1, c1 = (l4 >> 2) & 1,
              c2 = (l4 >> 1) & 1, c3 = l4 & 1;

    // --- Build phase 1: qubits 0..4 + layer-1 lane-RY fold -> M(k3,p) ---
    float M00, M01, M10, M11;   // M[k3][p]
    {
        float ecl[5], esl[5];
#pragma unroll
        for (int q = 0; q < 5; ++q) {
            const int di = q / 3 - 1, dj = q % 3 - 1;
            const int hi = shh + di, wj = sw + dj;
            float px = 0.0f;
            if ((unsigned)hi < 32u && (unsigned)wj < 32u)
                px = x[((b * 32 + hi) * 32 + wj) * 3 + c];
            __sincosf(fmaf(1.5707963267948966f, px, s_h0[c][q]), &esl[q], &ecl[q]);
        }
        const float t0 = s_vt[0][c][0], t1 = s_vt[0][c][1],
                    t2 = s_vt[0][c][2], t3 = s_vt[0][c][3];
        const float u0 = c0 ? t0 : -t0;
        const float u1 = c1 ? t1 : -t1;
        const float u2 = c2 ? t2 : -t2;
        const float u3 = c3 ? t3 : -t3;
        const int b2 = c2 ^ c1, b3 = c3 ^ c2;
        const float F2a = b2 ? esl[2] : ecl[2], F2b = b2 ? ecl[2] : esl[2];
        const float F3a = b3 ? esl[3] : ecl[3], F3b = b3 ? ecl[3] : esl[3];
        const float F4a = c3 ? esl[4] : ecl[4], F4b = c3 ? ecl[4] : esl[4];
#pragma unroll
        for (int p = 0; p < 2; ++p) {
            const int b0 = c0 ^ p, b1 = (c1 ^ c0) ^ p;
            const float F0a = b0 ? esl[0] : ecl[0], F0b = b0 ? ecl[0] : esl[0];
            const float F1a = b1 ? esl[1] : ecl[1], F1b = b1 ? ecl[1] : esl[1];
            const float D10 = fmaf(u0, F0b * F1b, F0a * F1a);
            const float D11 = fmaf(u0, F0b * F1a, F0a * F1b);
            const float D20 = fmaf(u1, D11 * F2b, D10 * F2a);
            const float D21 = fmaf(u1, D11 * F2a, D10 * F2b);
            const float D30 = fmaf(u2, D21 * F3b, D20 * F3a);
            const float D31 = fmaf(u2, D21 * F3a, D20 * F3b);
            const float m0 = fmaf(u3, D31 * F4b, D30 * F4a);   // k3=0
            const float m1 = fmaf(u3, D31 * F4a, D30 * F4b);   // k3=1
            if (p == 0) { M00 = m0; M10 = m1; }
            else        { M01 = m0; M11 = m1; }
        }
    }

    // --- Build phase 2: qubits 5..8 -> per-k factors, write state ---
    u64 st[16];
    {
        float ech[4], esh[4];
#pragma unroll
        for (int q = 5; q < 9; ++q) {
            const int di = q / 3 - 1, dj = q % 3 - 1;
            const int hi = shh + di, wj = sw + dj;
            float px = 0.0f;
            if ((unsigned)hi < 32u && (unsigned)wj < 32u)
                px = x[((b * 32 + hi) * 32 + wj) * 3 + c];
            __sincosf(fmaf(1.5707963267948966f, px, s_h0[c][q]), &esh[q - 5], &ech[q - 5]);
        }
        const u64 MM0 = pack2(M00, M01);         // k3=0: (p=0, p=1)
        const u64 MM1 = pack2(M10, M11);         // k3=1
        const u64 T8a = pack2(ech[3], esh[3]);   // k0=0: b8=p
        const u64 T8b = pack2(esh[3], ech[3]);   // k0=1: b8=p^1
#pragma unroll
        for (int k = 0; k < 16; ++k) {
            const int k3 = (k >> 3) & 1, k2 = (k >> 2) & 1,
                      k1 = (k >> 1) & 1, k0 = k & 1;
            const float m = ((k2 ^ k3) ? esh[0] : ech[0]) *
                            ((k1 ^ k2) ? esh[1] : ech[1]) *
                            ((k0 ^ k1) ? esh[2] : ech[2]);
            st[k] = mul2(mul2(k3 ? MM1 : MM0, pack2(m, m)), k0 ? T8b : T8a);
        }
    }

    const int lam4 = l4 ^ (l4 >> 1) ^ (l4 >> 2) ^ (l4 >> 3);

    // ========== Layer 1 (lane RYs already folded into the build) ==========
    // reg RYs q4..q7: a' = a - t*b ; b' = b + t*a
#pragma unroll
    for (int q = 4; q < 8; ++q) {
        const int m2 = 1 << (7 - q);
        const float t = s_vt[0][c][q];
        const u64 tp = pack2(t, t), tn = pack2(-t, -t);
#pragma unroll
        for (int k = 0; k < 16; ++k)
            if (!(k & m2)) {
                const u64 a = st[k], bb = st[k + m2];
                st[k]      = fma2(tn, bb, a);
                st[k + m2] = fma2(tp, a, bb);
            }
    }
    // pair RY q8: st' = st + (-t,+t)*swap(st)
    {
        const float t = s_vt[0][c][8];
        const u64 tpm = pack2(-t, t);
#pragma unroll
        for (int k = 0; k < 16; ++k) {
            float a, bb; unpack2(st[k], a, bb);
            st[k] = fma2(tpm, pack2(bb, a), st[k]);
        }
    }

    // --- Layer-1 CNOT ring ---
    // q0..q3 lane segment: DEFERRED. q3->q4: ctrl = popc(l4)&1, tgt k bit 3.
    {
        const bool hi = (__popc(l4) & 1) != 0;
#pragma unroll
        for (int k = 0; k < 8; ++k) {
            const u64 a = st[k], bb = st[k + 8];
            st[k]     = hi ? bb : a;
            st[k + 8] = hi ? a : bb;
        }
    }
    // q4->5, q5->6, q6->7: register renames (free)
    { u64 t;
      t = st[ 8]; st[ 8] = st[12]; st[12] = t;
      t = st[ 9]; st[ 9] = st[13]; st[13] = t;
      t = st[10]; st[10] = st[14]; st[14] = t;
      t = st[11]; st[11] = st[15]; st[15] = t; }
    { u64 t;
      t = st[ 4]; st[ 4] = st[ 6]; st[ 6] = t;
      t = st[ 5]; st[ 5] = st[ 7]; st[ 7] = t;
      t = st[12]; st[12] = st[14]; st[14] = t;
      t = st[13]; st[13] = st[15]; st[15] = t; }
    { u64 t;
      t = st[ 2]; st[ 2] = st[ 3]; st[ 3] = t;
      t = st[ 6]; st[ 6] = st[ 7]; st[ 7] = t;
      t = st[10]; st[10] = st[11]; st[11] = t;
      t = st[14]; st[14] = st[15]; st[15] = t; }
    // q7->q8: half-swap odd-k vecs
#pragma unroll
    for (int k = 1; k < 16; k += 2) {
        float a, bb; unpack2(st[k], a, bb);
        st[k] = pack2(bb, a);
    }
    // q8->q0 ring shuffle FUSED into layer-2 q0 below.

    // ========== Layer 2 (deferred space, tangent form) ==========
    // q0 lane RY fused with ring q8->0 (both physical mask 12, exact f32):
    //   a' = a + u*shfl(a,12) ;  b' = shfl(B,12) + u*B   (B = pre-ring b-half)
    {
        const float t = s_vt[1][c][0];
        const float u = (lam4 & 8) ? t : -t;
#pragma unroll
        for (int k = 0; k < 16; ++k) {
            float a, bb; unpack2(st[k], a, bb);
            const float pa = __shfl_xor_sync(FULL_MASK, a, 12);
            const float pB = __shfl_xor_sync(FULL_MASK, bb, 12);
            st[k] = pack2(fmaf(u, pa, a), fmaf(u, bb, pB));
        }
    }
    // q1..q3 lane RYs (plain f32 exchanges; physical masks pi(m)=m^(m>>1))
    {
        const int pmask[3] = {6, 3, 1};
        const int lmask[3] = {4, 2, 1};
#pragma unroll
        for (int qq = 0; qq < 3; ++qq) {
            const int pm = pmask[qq];
            const float t = s_vt[1][c][qq + 1];
            const float sts = (lam4 & lmask[qq]) ? t : -t;
            const u64 t2 = pack2(sts, sts);
#pragma unroll
            for (int k = 0; k < 16; ++k) {
                float a, bb; unpack2(st[k], a, bb);
                const float pa = __shfl_xor_sync(FULL_MASK, a, pm);
                const float pb = __shfl_xor_sync(FULL_MASK, bb, pm);
                st[k] = fma2(t2, pack2(pa, pb), st[k]);
            }
        }
    }
    // reg RYs q4..q7
#pragma unroll
    for (int q = 4; q < 8; ++q) {
        const int m2 = 1 << (7 - q);
        const float t = s_vt[1][c][q];
        const u64 tp = pack2(t, t), tn = pack2(-t, -t);
#pragma unroll
        for (int k = 0; k < 16; ++k)
            if (!(k & m2)) {
                const u64 a = st[k], bb = st[k + m2];
                st[k]      = fma2(tn, bb, a);
                st[k + m2] = fma2(tp, a, bb);
            }
    }
    // pair RY q8
    {
        const float t = s_vt[1][c][8];
        const u64 tpm = pack2(-t, t);
#pragma unroll
        for (int k = 0; k < 16; ++k) {
            float a, bb; unpack2(st[k], a, bb);
            st[k] = fma2(tpm, pack2(bb, a), st[k]);
        }
    }

    // --- Measurement (diagonal Pauli strings; cos product restored as S^2) ---
    u64 accE = 0ull, accO = 0ull;
#pragma unroll
    for (int k = 0; k < 16; ++k) {
        const u64 p = mul2(st[k], st[k]);
        if ((0x9669 >> k) & 1) accE = add2(accE, p);   // popc(k) even
        else                   accO = add2(accO, p);
    }
    float e0, e1, o0, o1;
    unpack2(accE, e0, e1); unpack2(accO, o0, o1);
    const float s2 = s_s2[c];
    const float sp = e0 + o1, sm = e1 + o0;
    const float tot = (sp + sm) * s2;
    const float dif = (sp - sm) * s2;

    // z0: per-half 4-level reduce
    float u = (__popc(lam4 & 7) & 1) ? -dif : dif;
    u += __shfl_xor_sync(FULL_MASK, u, 8);
    u += __shfl_xor_sync(FULL_MASK, u, 4);
    u += __shfl_xor_sync(FULL_MASK, u, 2);
    u += __shfl_xor_sync(FULL_MASK, u, 1);

    // z1/z2 factored: reduce over lam1-class subgroup {1,6,10}, cross mask 2
    float y = (__popc(lam4 & 12) & 1) ? -tot : tot;
    y += __shfl_xor_sync(FULL_MASK, y, 1);
    y += __shfl_xor_sync(FULL_MASK, y, 6);
    y += __shfl_xor_sync(FULL_MASK, y, 10);
    const float w = __shfl_xor_sync(FULL_MASK, y, 2);

    if (l4 == 0) {                       // lanes 0 (site A) and 16 (site B)
        const int base = 3 * (((b * 32 + shh) * 32 + 2 * wp + s) * 3 + c);
        out[base + 0] = u;
        out[base + 1] = y + w;           // lam4(0)=0 -> lam1-class 0
        out[base + 2] = y - w;
    }
}

extern "C" void kernel_launch(void* const* d_in, const int* in_sizes, int n_in,
                              void* d_out, int out_size) {
    const float* x  = (const float*)d_in[0];
    const float* qp = (const float*)d_in[1];
    float* out = (float*)d_out;
    // 12288 site-pair warps / 4 warps per 128-thread block = 3072 blocks
    quanv_main<<<3072, 128>>>(x, qp, out);
}